// round 15
// baseline (speedup 1.0000x reference)
#include <cuda_runtime.h>

typedef unsigned long long ull;

// ---------------- packed f32x2 helpers (Blackwell FFMA2 path) ----------------
__device__ __forceinline__ ull pack2(float a, float b) {
    ull r; asm("mov.b64 %0, {%1,%2};" : "=l"(r) : "f"(a), "f"(b)); return r;
}
__device__ __forceinline__ float2 unpack2(ull v) {
    float2 f; asm("mov.b64 {%0,%1}, %2;" : "=f"(f.x), "=f"(f.y) : "l"(v)); return f;
}
__device__ __forceinline__ ull ffma2(ull a, ull b, ull c) {
    ull d; asm("fma.rn.f32x2 %0, %1, %2, %3;" : "=l"(d) : "l"(a), "l"(b), "l"(c)); return d;
}
__device__ __forceinline__ ull fadd2(ull a, ull b) {
    ull d; asm("add.rn.f32x2 %0, %1, %2;" : "=l"(d) : "l"(a), "l"(b)); return d;
}

// HW tanh (single MUFU op); validated rel_err ~7e-7 end-to-end
__device__ __forceinline__ float tanh_fast(float x) {
    float y; asm("tanh.approx.f32 %0, %1;" : "=f"(y) : "f"(x)); return y;
}
__device__ __forceinline__ float sig_fast(float x) {
    return fmaf(0.5f, tanh_fast(0.5f * x), 0.5f);
}
__device__ __forceinline__ float sigmoidf_acc(float x) {
    return __fdividef(1.f, 1.f + __expf(-x));
}

#define B_  256
#define S_  1024
#define F_  64
#define H_  64
#define G_  256   // 4*H

// Pair mapping: pair index p -> u = p>>1, s = p&1
//   s=0: columns (u,     u+64 ) = (z_i[u],  z_f[u])
//   s=1: columns (u+128, u+192) = (z_c[u],  z_o[u])
// xz scratch: [t][b][p] packed float2 (col c0, col c1). 268MB.
__device__ ull   g_xz[(size_t)S_ * B_ * 128];
// h scratch: [b][t][u] floats. 64MB.
__device__ float g_h[(size_t)B_ * S_ * H_];

// =====================================================================
// Kernel A: xz = x @ kernel + bias — SPLIT-K to cut x-broadcast 4x.
// 1024 CTAs x 256 thr, 64 iters x 4 rows (quad).
// Matvec phase: warp w -> k-chunk kc=w&3 (16 k), rows {2rh, 2rh+1};
//   lane owns pairs {l, l+32, l+64, l+96}; partials -> psum.
// Reduce phase (round-7 identity): thread (j, half) sums 4 chunk
//   partials for pair j, rows half & half+2; adds bias; STG.
// =====================================================================
__global__ void __launch_bounds__(256, 1) lstm_xgemm(
    const float* __restrict__ x, const float* __restrict__ kern,
    const float* __restrict__ bias)
{
    const int tid  = threadIdx.x;
    const int lane = tid & 31;
    const int w    = tid >> 5;
    const int kc   = w & 3;             // k-chunk: k in [16kc, 16kc+16)
    const int rh   = w >> 2;            // rows 2rh, 2rh+1

    // matvec weights: 4 pairs x 2 cols x 8 k-pair ull = 64 ull
    ull wk[4][2][8];
#pragma unroll
    for (int pp = 0; pp < 4; pp++) {
        const int p  = lane + 32 * pp;
        const int pu = p >> 1, ps = p & 1;
        const int c0 = pu + (ps ? 128 : 0);
        const int c1 = c0 + 64;
#pragma unroll
        for (int m = 0; m < 8; m++) {
            const int k = 16 * kc + 2 * m;
            wk[pp][0][m] = pack2(kern[k * G_ + c0], kern[(k + 1) * G_ + c0]);
            wk[pp][1][m] = pack2(kern[k * G_ + c1], kern[(k + 1) * G_ + c1]);
        }
    }

    // reduce-phase identity
    const int j    = tid & 127;
    const int half = tid >> 7;
    const int ju   = j >> 1, js = j & 1;
    const int jc0  = ju + (js ? 128 : 0);
    const ull bj   = pack2(bias[jc0], bias[jc0 + 64]);

    __shared__ __align__(16) ull xpk[4][4][32];    // [slot][row][kpair] x ring
    __shared__ __align__(16) ull psum[4][4][128];  // [row][kc][pair] partials

    const int lr = (tid >> 5) & 3;
    const int lm = tid & 31;
    const int qbase = blockIdx.x * 64;

    float2 v = make_float2(0.f, 0.f);
    if (tid < 128) {
        float2 t0 = *(const float2*)(x + (size_t)((qbase + 0) * 4 + lr) * F_ + 2 * lm);
        xpk[0][lr][lm] = pack2(t0.x, t0.y);
        float2 t1 = *(const float2*)(x + (size_t)((qbase + 1) * 4 + lr) * F_ + 2 * lm);
        xpk[1][lr][lm] = pack2(t1.x, t1.y);
        v = *(const float2*)(x + (size_t)((qbase + 2) * 4 + lr) * F_ + 2 * lm);
    }
    __syncthreads();

#pragma unroll 4
    for (int i = 0; i < 64; i++) {
        // publish quad i+2 into ring slot (disjoint from slot i), prefetch i+3
        if (tid < 128 && i + 2 < 64) {
            xpk[(i + 2) & 3][lr][lm] = pack2(v.x, v.y);
            if (i + 3 < 64)
                v = *(const float2*)(x + (size_t)((qbase + i + 3) * 4 + lr) * F_ + 2 * lm);
        }

        // ---- matvec phase: own k-chunk only (16 broadcast LDS.64) ----
        const ull* xr0 = xpk[i & 3][2 * rh]     + 8 * kc;
        const ull* xr1 = xpk[i & 3][2 * rh + 1] + 8 * kc;
        ull acc[4][2][2];                       // [pp][row][col]
#pragma unroll
        for (int pp = 0; pp < 4; pp++)
            acc[pp][0][0] = acc[pp][0][1] = acc[pp][1][0] = acc[pp][1][1] = 0ull;
#pragma unroll
        for (int m = 0; m < 8; m++) {
            const ull x0 = xr0[m], x1 = xr1[m];
#pragma unroll
            for (int pp = 0; pp < 4; pp++) {
                acc[pp][0][0] = ffma2(wk[pp][0][m], x0, acc[pp][0][0]);
                acc[pp][0][1] = ffma2(wk[pp][1][m], x0, acc[pp][0][1]);
                acc[pp][1][0] = ffma2(wk[pp][0][m], x1, acc[pp][1][0]);
                acc[pp][1][1] = ffma2(wk[pp][1][m], x1, acc[pp][1][1]);
            }
        }
#pragma unroll
        for (int pp = 0; pp < 4; pp++) {
#pragma unroll
            for (int rr = 0; rr < 2; rr++) {
                const float2 f0 = unpack2(acc[pp][rr][0]);
                const float2 f1 = unpack2(acc[pp][rr][1]);
                psum[2 * rh + rr][kc][lane + 32 * pp] = pack2(f0.x + f0.y, f1.x + f1.y);
            }
        }
        __syncthreads();

        // ---- reduce phase: pair j, rows half & half+2 ----
        const ull r0 = fadd2(bj, fadd2(fadd2(psum[half][0][j],     psum[half][1][j]),
                                       fadd2(psum[half][2][j],     psum[half][3][j])));
        const ull r1 = fadd2(bj, fadd2(fadd2(psum[half + 2][0][j], psum[half + 2][1][j]),
                                       fadd2(psum[half + 2][2][j], psum[half + 2][3][j])));

        const int n0 = (qbase + i) * 4 + half;   // global row = b*S + t
        const int n1 = n0 + 2;
        {
            const int bb = n0 >> 10, tt = n0 & 1023;
            g_xz[((size_t)tt * B_ + bb) * 128 + j] = r0;
        }
        {
            const int bb = n1 >> 10, tt = n1 & 1023;
            g_xz[((size_t)tt * B_ + bb) * 128 + j] = r1;
        }
        __syncthreads();
    }
}

// =====================================================================
// Kernel B: LSTM recurrence — SPLIT-K matvec (h-broadcast cut 4x).
// 128 CTAs x 256 thr (2 rows/CTA, uniform 1 CTA/SM), named bars per row.
// Matvec: warp (r, kc): 8 broadcast LDS.64 of its h chunk, 64 FFMA2,
//   partials -> psum. Reduce+gates: round-7 identity (pair p = tid&127),
//   shfl gate exchange, depth-8 z ring, h streamed to g_h.
// =====================================================================
__global__ void __launch_bounds__(256, 1) lstm_recur(
    const float* __restrict__ rec)
{
    const int tid  = threadIdx.x;
    const int lane = tid & 31;
    const int kc   = (tid >> 5) & 3;     // k-chunk
    const int r    = tid >> 7;           // row
    const int brow = blockIdx.x * 2 + r;

    // matvec weights: 4 pairs x 2 cols x 8 ull = 64 ull
    ull wr[4][2][8];
#pragma unroll
    for (int pp = 0; pp < 4; pp++) {
        const int p  = lane + 32 * pp;
        const int pu = p >> 1, ps = p & 1;
        const int c0 = pu + (ps ? 128 : 0);
        const int c1 = c0 + 64;
#pragma unroll
        for (int m = 0; m < 8; m++) {
            const int k = 16 * kc + 2 * m;
            wr[pp][0][m] = pack2(rec[k * G_ + c0], rec[(k + 1) * G_ + c0]);
            wr[pp][1][m] = pack2(rec[k * G_ + c1], rec[(k + 1) * G_ + c1]);
        }
    }

    // reduce/gate-phase identity (round-7)
    const int p = tid & 127;
    const int u = p >> 1;
    const int s = p & 1;

    __shared__ __align__(16) ull hpk[2][2][32];    // [parity][row][m]
    __shared__ __align__(16) ull psum[2][4][128];  // [row][kc][pair]

    if (tid < 64) hpk[1][tid >> 5][tid & 31] = 0ull;   // h(-1)=0 at parity 1

    float c = 0.f;
    const size_t ZS = (size_t)B_ * 128;
    const ull* zp = g_xz + (size_t)brow * 128 + p;
    float* hout = g_h + (size_t)brow * S_ * H_ + u;

    // depth-8 z prefetch ring
    ull zr[8];
#pragma unroll
    for (int d = 0; d < 8; d++) zr[d] = zp[(size_t)d * ZS];
    zp += 8 * ZS;
    __syncthreads();

    const int barid = r + 1;      // named barrier per row (128 threads)

#pragma unroll 8
    for (int t = 0; t < S_; t++) {
        const ull zcur = zr[t & 7];              // z issued 8 steps ago
        if (t + 8 < S_) zr[t & 7] = *zp;
        zp += ZS;

        // ---- matvec phase: own k-chunk (8 broadcast LDS.64) ----
        const ull* hp = hpk[(t & 1) ^ 1][r] + 8 * kc;
        ull a00 = 0, a01 = 0, a10 = 0, a11 = 0,
            a20 = 0, a21 = 0, a30 = 0, a31 = 0;
#pragma unroll
        for (int m = 0; m < 8; m++) {
            const ull hm = hp[m];
            a00 = ffma2(wr[0][0][m], hm, a00);
            a01 = ffma2(wr[0][1][m], hm, a01);
            a10 = ffma2(wr[1][0][m], hm, a10);
            a11 = ffma2(wr[1][1][m], hm, a11);
            a20 = ffma2(wr[2][0][m], hm, a20);
            a21 = ffma2(wr[2][1][m], hm, a21);
            a30 = ffma2(wr[3][0][m], hm, a30);
            a31 = ffma2(wr[3][1][m], hm, a31);
        }
        {
            const float2 f00 = unpack2(a00), f01 = unpack2(a01);
            psum[r][kc][lane]      = pack2(f00.x + f00.y, f01.x + f01.y);
            const float2 f10 = unpack2(a10), f11 = unpack2(a11);
            psum[r][kc][lane + 32] = pack2(f10.x + f10.y, f11.x + f11.y);
            const float2 f20 = unpack2(a20), f21 = unpack2(a21);
            psum[r][kc][lane + 64] = pack2(f20.x + f20.y, f21.x + f21.y);
            const float2 f30 = unpack2(a30), f31 = unpack2(a31);
            psum[r][kc][lane + 96] = pack2(f30.x + f30.y, f31.x + f31.y);
        }
        asm volatile("bar.sync %0, 128;" :: "r"(barid) : "memory");

        // ---- reduce + gates phase (round-7 identity) ----
        const ull zfull = fadd2(zcur,
                           fadd2(fadd2(psum[r][0][p], psum[r][1][p]),
                                 fadd2(psum[r][2][p], psum[r][3][p])));
        const float2 zv = unpack2(zfull);        // (z_i|z_c, z_f|z_o)

        const float g0 = s ? tanh_fast(zv.x) : sig_fast(zv.x);
        const float g1 = sig_fast(zv.y);
        const float t0 = __shfl_xor_sync(0xffffffffu, g0, 1);
        const float t1 = __shfl_xor_sync(0xffffffffu, g1, 1);

        if (s == 0) {                            // lane holds (i,f); partner sent (tc,o)
            c = fmaf(g1, c, g0 * t0);
            const float h = t1 * tanh_fast(c);
            ((float*)hpk[t & 1][r])[u] = h;      // publish h_u(t)
            hout[(size_t)t * H_] = h;            // stream to gmem (off-chain STG)
        }
        asm volatile("bar.sync %0, 128;" :: "r"(barid) : "memory");
    }
}

// =====================================================================
// Kernel C: dense head  out[b,t] = sigmoid(h[b,t,:]·dw + db)
// One warp per output, coalesced float2 loads, shfl reduce.
// =====================================================================
__global__ void __launch_bounds__(256, 4) lstm_head(
    const float* __restrict__ dw, const float* __restrict__ db,
    float* __restrict__ out)
{
    const int lane = threadIdx.x & 31;
    const int o    = blockIdx.x * 8 + (threadIdx.x >> 5);   // output index b*S+t

    const float2 hv = *(const float2*)(g_h + (size_t)o * H_ + 2 * lane);
    const float2 wv = *(const float2*)(dw + 2 * lane);
    float pd = hv.x * wv.x + hv.y * wv.y;
#pragma unroll
    for (int off = 16; off; off >>= 1)
        pd += __shfl_xor_sync(0xffffffffu, pd, off);
    if (lane == 0)
        out[o] = sigmoidf_acc(pd + db[0]);
}

// =====================================================================
extern "C" void kernel_launch(void* const* d_in, const int* in_sizes, int n_in,
                              void* d_out, int out_size)
{
    const float* x    = (const float*)d_in[0];  // [256,1024,64]
    const float* kern = (const float*)d_in[1];  // [64,256]
    const float* rec  = (const float*)d_in[2];  // [64,256]
    const float* bias = (const float*)d_in[3];  // [256]
    const float* dw   = (const float*)d_in[4];  // [64,1]
    const float* db   = (const float*)d_in[5];  // [1]
    float* out = (float*)d_out;                 // [256,1024,1]

    lstm_xgemm<<<1024, 256>>>(x, kern, bias);
    lstm_recur<<<128, 256>>>(rec);
    lstm_head<<<(B_ * S_) / 8, 256>>>(dw, db, out);
}

// round 16
// speedup vs baseline: 1.1770x; 1.1770x over previous
#include <cuda_runtime.h>

typedef unsigned long long ull;

// ---------------- packed f32x2 helpers ----------------
__device__ __forceinline__ ull pack2(float a, float b) {
    ull r; asm("mov.b64 %0, {%1,%2};" : "=l"(r) : "f"(a), "f"(b)); return r;
}
__device__ __forceinline__ float2 unpack2(ull v) {
    float2 f; asm("mov.b64 {%0,%1}, %2;" : "=f"(f.x), "=f"(f.y) : "l"(v)); return f;
}
__device__ __forceinline__ ull ffma2(ull a, ull b, ull c) {
    ull d; asm("fma.rn.f32x2 %0, %1, %2, %3;" : "=l"(d) : "l"(a), "l"(b), "l"(c)); return d;
}
__device__ __forceinline__ ull fadd2(ull a, ull b) {
    ull d; asm("add.rn.f32x2 %0, %1, %2;" : "=l"(d) : "l"(a), "l"(b)); return d;
}
__device__ __forceinline__ unsigned f2tf32(float f) {
    unsigned u; asm("cvt.rna.tf32.f32 %0, %1;" : "=r"(u) : "f"(f)); return u;
}

// HW tanh (single MUFU op); validated rel_err ~7e-7 end-to-end
__device__ __forceinline__ float tanh_fast(float x) {
    float y; asm("tanh.approx.f32 %0, %1;" : "=f"(y) : "f"(x)); return y;
}
__device__ __forceinline__ float sig_fast(float x) {
    return fmaf(0.5f, tanh_fast(0.5f * x), 0.5f);
}
__device__ __forceinline__ float sigmoidf_acc(float x) {
    return __fdividef(1.f, 1.f + __expf(-x));
}

// D += A(tf32) * B(tf32), m16n8k8, fp32 accumulate
#define MMA_TF32(d, a0, a1, a2, a3, b0, b1) \
    asm volatile("mma.sync.aligned.m16n8k8.row.col.f32.tf32.tf32.f32 " \
        "{%0,%1,%2,%3}, {%4,%5,%6,%7}, {%8,%9}, {%0,%1,%2,%3};" \
        : "+f"(d[0]), "+f"(d[1]), "+f"(d[2]), "+f"(d[3]) \
        : "r"(a0), "r"(a1), "r"(a2), "r"(a3), "r"(b0), "r"(b1))

#define B_  256
#define S_  1024
#define F_  64
#define H_  64
#define G_  256   // 4*H

// Pair mapping: pair index p -> u = p>>1, s = p&1
//   s=0: columns (u,     u+64 ) = (z_i[u],  z_f[u])
//   s=1: columns (u+128, u+192) = (z_c[u],  z_o[u])
// xz scratch: [t][b][p] packed float2 (col c0, col c1). 268MB.
__device__ ull   g_xz[(size_t)S_ * B_ * 128];
// h scratch: [b][t][u] floats. 64MB.
__device__ float g_h[(size_t)B_ * S_ * H_];

// =====================================================================
// Kernel A: xz = x @ kernel + bias — TENSOR CORES, 3xTF32 for fp32 acc.
// 2048 CTAs x 256 thr; CTA = 128 rows = 8 iters x 16-row A-tile.
// Warp w owns units [8w, 8w+8): gate tiles I/F/C/O at cols 8w+64*gt.
// B fragments (hi+lo tf32) live in registers; per iter: 96 MMAs.
// =====================================================================
__global__ void __launch_bounds__(256, 1) lstm_xgemm(
    const float* __restrict__ x, const float* __restrict__ kern,
    const float* __restrict__ bias)
{
    const int tid  = threadIdx.x;
    const int w    = tid >> 5;       // warp: unit range [8w, 8w+8)
    const int lane = tid & 31;
    const int g    = lane >> 2;      // groupID 0..7
    const int tig  = lane & 3;       // thread-in-group 0..3
    const int colI = 8 * w;          // I-gate column base; gate gt adds 64*gt

    // ---- B fragments: [gate][kstep][2], tf32 hi and lo ----
    unsigned bh[4][8][2], bl[4][8][2];
#pragma unroll
    for (int gt = 0; gt < 4; gt++) {
        const int col = colI + 64 * gt + g;
#pragma unroll
        for (int ks = 0; ks < 8; ks++) {
            const float v0 = kern[(8 * ks + tig) * G_ + col];
            const float v1 = kern[(8 * ks + tig + 4) * G_ + col];
            const unsigned h0 = f2tf32(v0), h1 = f2tf32(v1);
            bh[gt][ks][0] = h0;
            bh[gt][ks][1] = h1;
            bl[gt][ks][0] = f2tf32(v0 - __uint_as_float(h0));
            bl[gt][ks][1] = f2tf32(v1 - __uint_as_float(h1));
        }
    }
    float bias0[4], bias1[4];
#pragma unroll
    for (int gt = 0; gt < 4; gt++) {
        bias0[gt] = bias[colI + 64 * gt + 2 * tig];
        bias1[gt] = bias[colI + 64 * gt + 2 * tig + 1];
    }

    // A staging: 16 rows x 64 cols, stride 68 (bank-conflict-free frags)
    __shared__ __align__(16) float As[2][16 * 68];

    const int rowbase0 = blockIdx.x * 128;
    const int lrow = tid >> 4;           // loader row 0..15
    const int lcol = (tid & 15) * 4;     // loader col 0..60

    float4 v = *(const float4*)(x + (size_t)(rowbase0 + lrow) * F_ + lcol);

    for (int it = 0; it < 8; it++) {
        const int buf = it & 1;
        *(float4*)(&As[buf][lrow * 68 + lcol]) = v;
        __syncthreads();
        if (it + 1 < 8)
            v = *(const float4*)(x + (size_t)(rowbase0 + (it + 1) * 16 + lrow) * F_ + lcol);

        float acc[4][4];
#pragma unroll
        for (int gt = 0; gt < 4; gt++) {
            acc[gt][0] = bias0[gt]; acc[gt][1] = bias1[gt];
            acc[gt][2] = bias0[gt]; acc[gt][3] = bias1[gt];
        }

        const float* A = As[buf];
#pragma unroll
        for (int ks = 0; ks < 8; ks++) {
            const int cb = ks * 8;
            const float a0 = A[g * 68 + cb + tig];
            const float a1 = A[(g + 8) * 68 + cb + tig];
            const float a2 = A[g * 68 + cb + tig + 4];
            const float a3 = A[(g + 8) * 68 + cb + tig + 4];
            const unsigned ah0 = f2tf32(a0), ah1 = f2tf32(a1);
            const unsigned ah2 = f2tf32(a2), ah3 = f2tf32(a3);
            const unsigned al0 = f2tf32(a0 - __uint_as_float(ah0));
            const unsigned al1 = f2tf32(a1 - __uint_as_float(ah1));
            const unsigned al2 = f2tf32(a2 - __uint_as_float(ah2));
            const unsigned al3 = f2tf32(a3 - __uint_as_float(ah3));
#pragma unroll
            for (int gt = 0; gt < 4; gt++) {
                MMA_TF32(acc[gt], ah0, ah1, ah2, ah3, bh[gt][ks][0], bh[gt][ks][1]);
                MMA_TF32(acc[gt], ah0, ah1, ah2, ah3, bl[gt][ks][0], bl[gt][ks][1]);
                MMA_TF32(acc[gt], al0, al1, al2, al3, bh[gt][ks][0], bh[gt][ks][1]);
            }
        }

        // ---- epilogue: pack (I,F)/(C,O) pairs, 32B-contiguous STG.128 ----
        // acc[gt][0]=row g,col 2tig; [1]=row g,col 2tig+1; [2]/[3]=row g+8.
        const int n0 = rowbase0 + it * 16 + g;
        const int n1 = n0 + 8;
        const int u0 = 8 * w + 2 * tig;
        {
            const int bb = n0 >> 10, tt = n0 & 1023;
            ull* dst = g_xz + ((size_t)tt * B_ + bb) * 128 + 2 * u0;
            ulonglong2 o0, o1;
            o0.x = pack2(acc[0][0], acc[1][0]);   // p=2u0   : (z_i, z_f)
            o0.y = pack2(acc[2][0], acc[3][0]);   // p=2u0+1 : (z_c, z_o)
            o1.x = pack2(acc[0][1], acc[1][1]);   // p=2u0+2
            o1.y = pack2(acc[2][1], acc[3][1]);   // p=2u0+3
            *(ulonglong2*)dst       = o0;
            *(ulonglong2*)(dst + 2) = o1;
        }
        {
            const int bb = n1 >> 10, tt = n1 & 1023;
            ull* dst = g_xz + ((size_t)tt * B_ + bb) * 128 + 2 * u0;
            ulonglong2 o0, o1;
            o0.x = pack2(acc[0][2], acc[1][2]);
            o0.y = pack2(acc[2][2], acc[3][2]);
            o1.x = pack2(acc[0][3], acc[1][3]);
            o1.y = pack2(acc[2][3], acc[3][3]);
            *(ulonglong2*)dst       = o0;
            *(ulonglong2*)(dst + 2) = o1;
        }
    }
}

// =====================================================================
// Kernel B: LSTM recurrence — round-7 proven version VERBATIM
// (named bar per row, plain ull LDS, depth-8 z ring, 8 FFMA2 chains).
// 128 CTAs x 256 thr (2 rows/CTA, uniform 1 CTA/SM). h -> g_h.
// =====================================================================
__global__ void __launch_bounds__(256, 1) lstm_recur(
    const float* __restrict__ rec)
{
    const int tid  = threadIdx.x;
    const int p    = tid & 127;
    const int r    = tid >> 7;
    const int u    = p >> 1;
    const int s    = p & 1;
    const int brow = blockIdx.x * 2 + r;
    const int c0   = u + (s ? 128 : 0);
    const int c1   = c0 + 64;

    ull wA[32], wB[32];
#pragma unroll
    for (int m = 0; m < 32; m++) {
        wA[m] = pack2(rec[(2 * m) * G_ + c0], rec[(2 * m + 1) * G_ + c0]);
        wB[m] = pack2(rec[(2 * m) * G_ + c1], rec[(2 * m + 1) * G_ + c1]);
    }

    __shared__ __align__(16) ull hpk[2][2][32];   // [parity][row][m] = (h_2m, h_2m+1)

    if (tid < 64) hpk[1][tid >> 5][tid & 31] = 0ull;   // h(-1) = 0 at parity 1

    float c = 0.f;
    const size_t ZS = (size_t)B_ * 128;
    const ull* zp = g_xz + (size_t)brow * 128 + p;
    float* hout = g_h + (size_t)brow * S_ * H_ + u;    // [t][u] stream

    // depth-8 z prefetch ring
    ull zr[8];
#pragma unroll
    for (int d = 0; d < 8; d++) zr[d] = zp[(size_t)d * ZS];
    zp += 8 * ZS;
    __syncthreads();

    const int barid = r + 1;     // named barrier per row (128 threads each)

#pragma unroll 8
    for (int t = 0; t < S_; t++) {
        const int  pr = (t & 1) ^ 1;            // parity holding h(t-1)
        const ull* hp = hpk[pr][r];

        const ull zcur = zr[t & 7];             // z issued 8 steps ago
        if (t + 8 < S_) zr[t & 7] = *zp;
        zp += ZS;

        // matvec: 32 broadcast LDS + 64 FFMA2, 8 chains
        ull a0 = 0, a1 = 0, a2 = 0, a3 = 0;
        ull b0 = 0, b1 = 0, b2 = 0, b3 = 0;
#pragma unroll
        for (int m = 0; m < 32; m += 4) {
            const ull h0 = hp[m],     h1 = hp[m + 1];
            const ull h2 = hp[m + 2], h3 = hp[m + 3];
            a0 = ffma2(wA[m],     h0, a0);
            a1 = ffma2(wA[m + 1], h1, a1);
            a2 = ffma2(wB[m],     h0, a2);
            a3 = ffma2(wB[m + 1], h1, a3);
            b0 = ffma2(wA[m + 2], h2, b0);
            b1 = ffma2(wA[m + 3], h3, b1);
            b2 = ffma2(wB[m + 2], h2, b2);
            b3 = ffma2(wB[m + 3], h3, b3);
        }
        const float2 sa  = unpack2(fadd2(fadd2(a0, a1), fadd2(b0, b1)));
        const float2 sb  = unpack2(fadd2(fadd2(a2, a3), fadd2(b2, b3)));
        const float2 zin = unpack2(zcur);
        const float zv0 = zin.x + sa.x + sa.y;  // z_i (s=0) / z_c (s=1)
        const float zv1 = zin.y + sb.x + sb.y;  // z_f (s=0) / z_o (s=1)

        // own activations, then in-warp exchange with partner lane
        const float g0 = s ? tanh_fast(zv0) : sig_fast(zv0);
        const float g1 = sig_fast(zv1);
        const float t0 = __shfl_xor_sync(0xffffffffu, g0, 1);
        const float t1 = __shfl_xor_sync(0xffffffffu, g1, 1);

        if (s == 0) {                           // lane holds (i,f); partner sent (tc,o)
            c = fmaf(g1, c, g0 * t0);
            const float h = t1 * tanh_fast(c);
            ((float*)hpk[t & 1][r])[u] = h;     // publish h_u(t) for next step
            hout[(size_t)t * H_] = h;           // stream to gmem (off-chain STG)
        }
        asm volatile("bar.sync %0, 128;" :: "r"(barid) : "memory");
    }
}

// =====================================================================
// Kernel C: dense head  out[b,t] = sigmoid(h[b,t,:]·dw + db)
// One warp per output, coalesced float2 loads, shfl reduce.
// =====================================================================
__global__ void __launch_bounds__(256, 4) lstm_head(
    const float* __restrict__ dw, const float* __restrict__ db,
    float* __restrict__ out)
{
    const int lane = threadIdx.x & 31;
    const int o    = blockIdx.x * 8 + (threadIdx.x >> 5);   // output index b*S+t

    const float2 hv = *(const float2*)(g_h + (size_t)o * H_ + 2 * lane);
    const float2 wv = *(const float2*)(dw + 2 * lane);
    float pd = hv.x * wv.x + hv.y * wv.y;
#pragma unroll
    for (int off = 16; off; off >>= 1)
        pd += __shfl_xor_sync(0xffffffffu, pd, off);
    if (lane == 0)
        out[o] = sigmoidf_acc(pd + db[0]);
}

// =====================================================================
extern "C" void kernel_launch(void* const* d_in, const int* in_sizes, int n_in,
                              void* d_out, int out_size)
{
    const float* x    = (const float*)d_in[0];  // [256,1024,64]
    const float* kern = (const float*)d_in[1];  // [64,256]
    const float* rec  = (const float*)d_in[2];  // [64,256]
    const float* bias = (const float*)d_in[3];  // [256]
    const float* dw   = (const float*)d_in[4];  // [64,1]
    const float* db   = (const float*)d_in[5];  // [1]
    float* out = (float*)d_out;                 // [256,1024,1]

    lstm_xgemm<<<2048, 256>>>(x, kern, bias);
    lstm_recur<<<128, 256>>>(rec);
    lstm_head<<<(B_ * S_) / 8, 256>>>(dw, db, out);
}

// round 17
// speedup vs baseline: 1.2198x; 1.0364x over previous
#include <cuda_runtime.h>

typedef unsigned long long ull;

// ---------------- packed f32x2 helpers ----------------
__device__ __forceinline__ ull pack2(float a, float b) {
    ull r; asm("mov.b64 %0, {%1,%2};" : "=l"(r) : "f"(a), "f"(b)); return r;
}
__device__ __forceinline__ float2 unpack2(ull v) {
    float2 f; asm("mov.b64 {%0,%1}, %2;" : "=f"(f.x), "=f"(f.y) : "l"(v)); return f;
}
__device__ __forceinline__ ull ffma2(ull a, ull b, ull c) {
    ull d; asm("fma.rn.f32x2 %0, %1, %2, %3;" : "=l"(d) : "l"(a), "l"(b), "l"(c)); return d;
}
__device__ __forceinline__ ull fadd2(ull a, ull b) {
    ull d; asm("add.rn.f32x2 %0, %1, %2;" : "=l"(d) : "l"(a), "l"(b)); return d;
}
__device__ __forceinline__ unsigned f2tf32(float f) {
    unsigned u; asm("cvt.rna.tf32.f32 %0, %1;" : "=r"(u) : "f"(f)); return u;
}

// HW tanh (single MUFU op); validated rel_err ~7e-7 end-to-end
__device__ __forceinline__ float tanh_fast(float x) {
    float y; asm("tanh.approx.f32 %0, %1;" : "=f"(y) : "f"(x)); return y;
}
__device__ __forceinline__ float sig_fast(float x) {
    return fmaf(0.5f, tanh_fast(0.5f * x), 0.5f);
}
__device__ __forceinline__ float sigmoidf_acc(float x) {
    return __fdividef(1.f, 1.f + __expf(-x));
}

// D += A(tf32) * B(tf32), m16n8k8, fp32 accumulate
#define MMA_TF32(d, a0, a1, a2, a3, b0, b1) \
    asm volatile("mma.sync.aligned.m16n8k8.row.col.f32.tf32.tf32.f32 " \
        "{%0,%1,%2,%3}, {%4,%5,%6,%7}, {%8,%9}, {%0,%1,%2,%3};" \
        : "+f"(d[0]), "+f"(d[1]), "+f"(d[2]), "+f"(d[3]) \
        : "r"(a0), "r"(a1), "r"(a2), "r"(a3), "r"(b0), "r"(b1))

#define B_  256
#define S_  1024
#define F_  64
#define H_  64
#define G_  256   // 4*H

// Pair mapping: pair index p -> u = p>>1, s = p&1
//   s=0: columns (u,     u+64 ) = (z_i[u],  z_f[u])
//   s=1: columns (u+128, u+192) = (z_c[u],  z_o[u])
// xz scratch: [t][b][p] packed float2 (col c0, col c1). 268MB.
__device__ ull   g_xz[(size_t)S_ * B_ * 128];
// h scratch: [b][t][u] floats. 64MB.
__device__ float g_h[(size_t)B_ * S_ * H_];

// =====================================================================
// Kernel A: xz = x @ kernel + bias — 3xTF32 tensor cores, 2 A-TILES per
// iteration for 8 independent MMA chains per warp (round-16 had 4).
// 1024 CTAs x 256 thr; CTA = 256 rows = 8 iters x 32-row super-tile.
// Warp w owns units [8w, 8w+8): gate tiles I/F/C/O at cols 8w+64*gt.
// =====================================================================
__global__ void __launch_bounds__(256, 1) lstm_xgemm(
    const float* __restrict__ x, const float* __restrict__ kern,
    const float* __restrict__ bias)
{
    const int tid  = threadIdx.x;
    const int w    = tid >> 5;       // warp: unit range [8w, 8w+8)
    const int lane = tid & 31;
    const int g    = lane >> 2;      // groupID 0..7
    const int tig  = lane & 3;       // thread-in-group 0..3
    const int colI = 8 * w;          // I-gate column base; gate gt adds 64*gt

    // ---- B fragments: [gate][kstep][2], tf32 hi and lo (128 regs) ----
    unsigned bh[4][8][2], bl[4][8][2];
#pragma unroll
    for (int gt = 0; gt < 4; gt++) {
        const int col = colI + 64 * gt + g;
#pragma unroll
        for (int ks = 0; ks < 8; ks++) {
            const float v0 = kern[(8 * ks + tig) * G_ + col];
            const float v1 = kern[(8 * ks + tig + 4) * G_ + col];
            const unsigned h0 = f2tf32(v0), h1 = f2tf32(v1);
            bh[gt][ks][0] = h0;
            bh[gt][ks][1] = h1;
            bl[gt][ks][0] = f2tf32(v0 - __uint_as_float(h0));
            bl[gt][ks][1] = f2tf32(v1 - __uint_as_float(h1));
        }
    }
    float bias0[4], bias1[4];
#pragma unroll
    for (int gt = 0; gt < 4; gt++) {
        bias0[gt] = bias[colI + 64 * gt + 2 * tig];
        bias1[gt] = bias[colI + 64 * gt + 2 * tig + 1];
    }

    // A staging: 32 rows x 64 cols, stride 68 (conflict-free frag loads)
    __shared__ __align__(16) float As[2][32 * 68];

    const int rowbase0 = blockIdx.x * 256;
    const int lrow = tid >> 4;           // loader row 0..15 (also +16)
    const int lcol = (tid & 15) * 4;     // loader col 0..60

    float4 va = *(const float4*)(x + (size_t)(rowbase0 + lrow)      * F_ + lcol);
    float4 vb = *(const float4*)(x + (size_t)(rowbase0 + lrow + 16) * F_ + lcol);

    for (int it = 0; it < 8; it++) {
        const int buf = it & 1;
        *(float4*)(&As[buf][lrow * 68 + lcol])        = va;
        *(float4*)(&As[buf][(lrow + 16) * 68 + lcol]) = vb;
        __syncthreads();
        if (it + 1 < 8) {
            const int rb = rowbase0 + (it + 1) * 32;
            va = *(const float4*)(x + (size_t)(rb + lrow)      * F_ + lcol);
            vb = *(const float4*)(x + (size_t)(rb + lrow + 16) * F_ + lcol);
        }

        float acc[2][4][4];                 // [tile][gate][frag]
#pragma unroll
        for (int tl = 0; tl < 2; tl++)
#pragma unroll
            for (int gt = 0; gt < 4; gt++) {
                acc[tl][gt][0] = bias0[gt]; acc[tl][gt][1] = bias1[gt];
                acc[tl][gt][2] = bias0[gt]; acc[tl][gt][3] = bias1[gt];
            }

        const float* A = As[buf];
#pragma unroll
        for (int ks = 0; ks < 8; ks++) {
            const int cb = ks * 8;
#pragma unroll
            for (int tl = 0; tl < 2; tl++) {
                const int rb = 16 * tl;
                const float a0 = A[(rb + g)     * 68 + cb + tig];
                const float a1 = A[(rb + g + 8) * 68 + cb + tig];
                const float a2 = A[(rb + g)     * 68 + cb + tig + 4];
                const float a3 = A[(rb + g + 8) * 68 + cb + tig + 4];
                const unsigned ah0 = f2tf32(a0), ah1 = f2tf32(a1);
                const unsigned ah2 = f2tf32(a2), ah3 = f2tf32(a3);
                const unsigned al0 = f2tf32(a0 - __uint_as_float(ah0));
                const unsigned al1 = f2tf32(a1 - __uint_as_float(ah1));
                const unsigned al2 = f2tf32(a2 - __uint_as_float(ah2));
                const unsigned al3 = f2tf32(a3 - __uint_as_float(ah3));
#pragma unroll
                for (int gt = 0; gt < 4; gt++) {
                    MMA_TF32(acc[tl][gt], ah0, ah1, ah2, ah3, bh[gt][ks][0], bh[gt][ks][1]);
                    MMA_TF32(acc[tl][gt], ah0, ah1, ah2, ah3, bl[gt][ks][0], bl[gt][ks][1]);
                    MMA_TF32(acc[tl][gt], al0, al1, al2, al3, bh[gt][ks][0], bh[gt][ks][1]);
                }
            }
        }

        // ---- epilogue: pack (I,F)/(C,O) pairs, 32B-contiguous stores ----
        // acc[tl][gt][0]=row rb+g,col 2tig; [1]=col 2tig+1; [2]/[3]=row rb+g+8.
        const int u0 = 8 * w + 2 * tig;
#pragma unroll
        for (int tl = 0; tl < 2; tl++) {
            const int n0 = rowbase0 + it * 32 + 16 * tl + g;
            const int n1 = n0 + 8;
            {
                const int bb = n0 >> 10, tt = n0 & 1023;
                ull* dst = g_xz + ((size_t)tt * B_ + bb) * 128 + 2 * u0;
                ulonglong2 o0, o1;
                o0.x = pack2(acc[tl][0][0], acc[tl][1][0]);   // p=2u0   : (z_i, z_f)
                o0.y = pack2(acc[tl][2][0], acc[tl][3][0]);   // p=2u0+1 : (z_c, z_o)
                o1.x = pack2(acc[tl][0][1], acc[tl][1][1]);
                o1.y = pack2(acc[tl][2][1], acc[tl][3][1]);
                *(ulonglong2*)dst       = o0;
                *(ulonglong2*)(dst + 2) = o1;
            }
            {
                const int bb = n1 >> 10, tt = n1 & 1023;
                ull* dst = g_xz + ((size_t)tt * B_ + bb) * 128 + 2 * u0;
                ulonglong2 o0, o1;
                o0.x = pack2(acc[tl][0][2], acc[tl][1][2]);
                o0.y = pack2(acc[tl][2][2], acc[tl][3][2]);
                o1.x = pack2(acc[tl][0][3], acc[tl][1][3]);
                o1.y = pack2(acc[tl][2][3], acc[tl][3][3]);
                *(ulonglong2*)dst       = o0;
                *(ulonglong2*)(dst + 2) = o1;
            }
        }
    }
}

// =====================================================================
// Kernel B: LSTM recurrence — round-7 proven version VERBATIM
// (named bar per row, plain ull LDS, depth-8 z ring, 8 FFMA2 chains).
// 128 CTAs x 256 thr (2 rows/CTA, uniform 1 CTA/SM). h -> g_h.
// =====================================================================
__global__ void __launch_bounds__(256, 1) lstm_recur(
    const float* __restrict__ rec)
{
    const int tid  = threadIdx.x;
    const int p    = tid & 127;
    const int r    = tid >> 7;
    const int u    = p >> 1;
    const int s    = p & 1;
    const int brow = blockIdx.x * 2 + r;
    const int c0   = u + (s ? 128 : 0);
    const int c1   = c0 + 64;

    ull wA[32], wB[32];
#pragma unroll
    for (int m = 0; m < 32; m++) {
        wA[m] = pack2(rec[(2 * m) * G_ + c0], rec[(2 * m + 1) * G_ + c0]);
        wB[m] = pack2(rec[(2 * m) * G_ + c1], rec[(2 * m + 1) * G_ + c1]);
    }

    __shared__ __align__(16) ull hpk[2][2][32];   // [parity][row][m] = (h_2m, h_2m+1)

    if (tid < 64) hpk[1][tid >> 5][tid & 31] = 0ull;   // h(-1) = 0 at parity 1

    float c = 0.f;
    const size_t ZS = (size_t)B_ * 128;
    const ull* zp = g_xz + (size_t)brow * 128 + p;
    float* hout = g_h + (size_t)brow * S_ * H_ + u;    // [t][u] stream

    // depth-8 z prefetch ring
    ull zr[8];
#pragma unroll
    for (int d = 0; d < 8; d++) zr[d] = zp[(size_t)d * ZS];
    zp += 8 * ZS;
    __syncthreads();

    const int barid = r + 1;     // named barrier per row (128 threads each)

#pragma unroll 8
    for (int t = 0; t < S_; t++) {
        const int  pr = (t & 1) ^ 1;            // parity holding h(t-1)
        const ull* hp = hpk[pr][r];

        const ull zcur = zr[t & 7];             // z issued 8 steps ago
        if (t + 8 < S_) zr[t & 7] = *zp;
        zp += ZS;

        // matvec: 32 broadcast LDS + 64 FFMA2, 8 chains
        ull a0 = 0, a1 = 0, a2 = 0, a3 = 0;
        ull b0 = 0, b1 = 0, b2 = 0, b3 = 0;
#pragma unroll
        for (int m = 0; m < 32; m += 4) {
            const ull h0 = hp[m],     h1 = hp[m + 1];
            const ull h2 = hp[m + 2], h3 = hp[m + 3];
            a0 = ffma2(wA[m],     h0, a0);
            a1 = ffma2(wA[m + 1], h1, a1);
            a2 = ffma2(wB[m],     h0, a2);
            a3 = ffma2(wB[m + 1], h1, a3);
            b0 = ffma2(wA[m + 2], h2, b0);
            b1 = ffma2(wA[m + 3], h3, b1);
            b2 = ffma2(wB[m + 2], h2, b2);
            b3 = ffma2(wB[m + 3], h3, b3);
        }
        const float2 sa  = unpack2(fadd2(fadd2(a0, a1), fadd2(b0, b1)));
        const float2 sb  = unpack2(fadd2(fadd2(a2, a3), fadd2(b2, b3)));
        const float2 zin = unpack2(zcur);
        const float zv0 = zin.x + sa.x + sa.y;  // z_i (s=0) / z_c (s=1)
        const float zv1 = zin.y + sb.x + sb.y;  // z_f (s=0) / z_o (s=1)

        // own activations, then in-warp exchange with partner lane
        const float g0 = s ? tanh_fast(zv0) : sig_fast(zv0);
        const float g1 = sig_fast(zv1);
        const float t0 = __shfl_xor_sync(0xffffffffu, g0, 1);
        const float t1 = __shfl_xor_sync(0xffffffffu, g1, 1);

        if (s == 0) {                           // lane holds (i,f); partner sent (tc,o)
            c = fmaf(g1, c, g0 * t0);
            const float h = t1 * tanh_fast(c);
            ((float*)hpk[t & 1][r])[u] = h;     // publish h_u(t) for next step
            hout[(size_t)t * H_] = h;           // stream to gmem (off-chain STG)
        }
        asm volatile("bar.sync %0, 128;" :: "r"(barid) : "memory");
    }
}

// =====================================================================
// Kernel C: dense head — 4 outputs per warp for MLP=4 on the h stream.
// out[b,t] = sigmoid(h[b,t,:]·dw + db).
// =====================================================================
__global__ void __launch_bounds__(256, 4) lstm_head(
    const float* __restrict__ dw, const float* __restrict__ db,
    float* __restrict__ out)
{
    const int lane  = threadIdx.x & 31;
    const int obase = (blockIdx.x * 8 + (threadIdx.x >> 5)) * 4;

    const float2 wv = *(const float2*)(dw + 2 * lane);
    const float  dbias = db[0];

    // 4 independent row loads in flight
    const float2 h0 = *(const float2*)(g_h + (size_t)(obase + 0) * H_ + 2 * lane);
    const float2 h1 = *(const float2*)(g_h + (size_t)(obase + 1) * H_ + 2 * lane);
    const float2 h2 = *(const float2*)(g_h + (size_t)(obase + 2) * H_ + 2 * lane);
    const float2 h3 = *(const float2*)(g_h + (size_t)(obase + 3) * H_ + 2 * lane);

    float p0 = h0.x * wv.x + h0.y * wv.y;
    float p1 = h1.x * wv.x + h1.y * wv.y;
    float p2 = h2.x * wv.x + h2.y * wv.y;
    float p3 = h3.x * wv.x + h3.y * wv.y;
#pragma unroll
    for (int off = 16; off; off >>= 1) {
        p0 += __shfl_xor_sync(0xffffffffu, p0, off);
        p1 += __shfl_xor_sync(0xffffffffu, p1, off);
        p2 += __shfl_xor_sync(0xffffffffu, p2, off);
        p3 += __shfl_xor_sync(0xffffffffu, p3, off);
    }
    if (lane == 0) {
        float4 o;
        o.x = sigmoidf_acc(p0 + dbias);
        o.y = sigmoidf_acc(p1 + dbias);
        o.z = sigmoidf_acc(p2 + dbias);
        o.w = sigmoidf_acc(p3 + dbias);
        *(float4*)(out + obase) = o;
    }
}

// =====================================================================
extern "C" void kernel_launch(void* const* d_in, const int* in_sizes, int n_in,
                              void* d_out, int out_size)
{
    const float* x    = (const float*)d_in[0];  // [256,1024,64]
    const float* kern = (const float*)d_in[1];  // [64,256]
    const float* rec  = (const float*)d_in[2];  // [64,256]
    const float* bias = (const float*)d_in[3];  // [256]
    const float* dw   = (const float*)d_in[4];  // [64,1]
    const float* db   = (const float*)d_in[5];  // [1]
    float* out = (float*)d_out;                 // [256,1024,1]

    lstm_xgemm<<<1024, 256>>>(x, kern, bias);
    lstm_recur<<<128, 256>>>(rec);
    lstm_head<<<(B_ * S_) / 32, 256>>>(dw, db, out);
}